// round 12
// baseline (speedup 1.0000x reference)
#include <cuda_runtime.h>
#include <cstdint>

// Problem constants
#define Bv 2
#define Sv 2048
#define Dv 1024
#define Hv 32
#define HDv 32
#define Mv (Bv*Sv)   // 4096

// Scratch (device globals -- no allocation allowed)
__device__ float g_Q[Bv*Hv*Sv*HDv];   // [b,h,s,hd]
__device__ float g_K[Bv*Hv*Sv*HDv];
__device__ float g_V[Bv*Hv*Sv*HDv];
// packed bf16 hi/lo operand planes (uint4 groups, 256 per row of K=1024)
__device__ uint4 g_xp[Mv * 256];          // x packed
__device__ uint4 g_wp[4][Dv * 256];       // wq,wk,wv,wo packed
__device__ uint4 g_op[Mv * 256];          // attn-out packed (written by flash)

// ---------------------------------------------------------------------------
// bf16 helpers (legacy mma.sync path -- works on plain sm_103 target)
// ---------------------------------------------------------------------------
__device__ __forceinline__ uint32_t pack_bf16x2(float e0, float e1) {
    uint32_t r;
    asm("cvt.rn.bf16x2.f32 %0, %1, %2;" : "=r"(r) : "f"(e1), "f"(e0));
    return r;
}
__device__ __forceinline__ float bf16lo_f(uint32_t u) { return __uint_as_float(u << 16); }
__device__ __forceinline__ float bf16hi_f(uint32_t u) { return __uint_as_float(u & 0xFFFF0000u); }

__device__ __forceinline__ void mma16n8k16_bf16(float* d, const uint32_t* a, const uint32_t* b) {
    asm volatile(
        "mma.sync.aligned.m16n8k16.row.col.f32.bf16.bf16.f32 "
        "{%0,%1,%2,%3}, {%4,%5,%6,%7}, {%8,%9}, {%0,%1,%2,%3};"
        : "+f"(d[0]), "+f"(d[1]), "+f"(d[2]), "+f"(d[3])
        : "r"(a[0]), "r"(a[1]), "r"(a[2]), "r"(a[3]), "r"(b[0]), "r"(b[1]));
}

__device__ __forceinline__ void split_pack_bf16(float e0, float e1, uint32_t& hi, uint32_t& lo) {
    hi = pack_bf16x2(e0, e1);
    lo = pack_bf16x2(e0 - bf16lo_f(hi), e1 - bf16hi_f(hi));
}

__device__ __forceinline__ uint32_t smem_u32(const void* p) {
    uint32_t a;
    asm("{ .reg .u64 t; cvta.to.shared.u64 t, %1; cvt.u32.u64 %0, t; }" : "=r"(a) : "l"(p));
    return a;
}

__device__ __forceinline__ void cp_async16(uint32_t saddr, const void* gptr) {
    asm volatile("cp.async.cg.shared.global [%0], [%1], 16;" :: "r"(saddr), "l"(gptr));
}

// ---------------------------------------------------------------------------
// Fused pack: rows 0..4095 = x; rows 4096.. = the 4 weight matrices.
// ---------------------------------------------------------------------------
__global__ __launch_bounds__(256) void pack_all(
    const float* __restrict__ x,
    const float* __restrict__ wq, const float* __restrict__ wk,
    const float* __restrict__ wv, const float* __restrict__ wo,
    uint4* __restrict__ xp, uint4* __restrict__ wp)
{
    const int bx = blockIdx.x;
    const float* src;
    uint4* dst;
    int row;
    if (bx < Mv) {
        src = x; dst = xp; row = bx;
    } else {
        const int wi = (bx - Mv) >> 10;
        row = (bx - Mv) & 1023;
        src = (wi == 0) ? wq : (wi == 1) ? wk : (wi == 2) ? wv : wo;
        dst = wp + (size_t)wi * Dv * 256;
    }
    const int rem = threadIdx.x;
    const int c = rem >> 3, gidx = rem & 7;
    const int ks = gidx >> 2, tg = gidx & 3;
    const float* p = src + (size_t)row * 1024 + c * 32 + ks * 16 + 2 * tg;
    const float2 a0 = *(const float2*)p;
    const float2 a1 = *(const float2*)(p + 8);
    uint32_t h0, l0, h1, l1;
    split_pack_bf16(a0.x, a0.y, h0, l0);
    split_pack_bf16(a1.x, a1.y, h1, l1);
    dst[(size_t)row * 256 + rem] = make_uint4(h0, h1, l0, l1);
}

// ---------------------------------------------------------------------------
// GEMM core (bf16 3-term, packed operands, cp.async double buffer).
// CTA tile 128x128, K-chunk 32, 8 warps (4m x 2n), warp tile 32x64.
// Single __syncthreads per chunk. (R10-verified.)
// ---------------------------------------------------------------------------
__device__ __forceinline__ void gemm_core(
    const uint4* __restrict__ Ap, const uint4* __restrict__ Wp,
    int m0, int n0, float acc[2][8][4])
{
    extern __shared__ uint4 sm[];
    const uint32_t sbase = smem_u32(sm);

    const int tid  = threadIdx.x;
    const int wid  = tid >> 5, lane = tid & 31;
    const int wm   = wid & 3,  wn   = wid >> 2;
    const int g    = lane >> 2, tg  = lane & 3;

    auto stage = [&](int c, int buf) {
        #pragma unroll
        for (int i = 0; i < 4; i++) {
            const int j = tid + i * 256;
            const int row = j >> 3, gi = j & 7;
            const uint32_t so = (uint32_t)(buf * 3072 + row * 12 + gi) * 16u;
            cp_async16(sbase + so,
                       Ap + (((size_t)(m0 + row)) << 8) + (c << 3) + gi);
            cp_async16(sbase + so + 1536u * 16u,
                       Wp + (((size_t)(n0 + row)) << 8) + (c << 3) + gi);
        }
        asm volatile("cp.async.commit_group;");
    };

    stage(0, 0);

    for (int c = 0; c < 32; c++) {
        asm volatile("cp.async.wait_group 0;");
        __syncthreads();
        if (c < 31) stage(c + 1, (c + 1) & 1);

        const uint4* SA = sm + (c & 1) * 3072;
        const uint4* SB = SA + 1536;

        #pragma unroll
        for (int ks = 0; ks < 2; ks++) {
            uint32_t ah[2][4], al[2][4];
            #pragma unroll
            for (int mt = 0; mt < 2; mt++) {
                const int r = wm * 32 + mt * 16 + g;
                const uint4 u1 = SA[r * 12 + ks * 4 + tg];
                const uint4 u2 = SA[(r + 8) * 12 + ks * 4 + tg];
                ah[mt][0] = u1.x; ah[mt][1] = u2.x; ah[mt][2] = u1.y; ah[mt][3] = u2.y;
                al[mt][0] = u1.z; al[mt][1] = u2.z; al[mt][2] = u1.w; al[mt][3] = u2.w;
            }
            #pragma unroll
            for (int nt = 0; nt < 8; nt++) {
                const int n = wn * 64 + nt * 8 + g;
                const uint4 ub = SB[n * 12 + ks * 4 + tg];
                uint32_t bh[2] = {ub.x, ub.y};
                uint32_t bl[2] = {ub.z, ub.w};
                #pragma unroll
                for (int mt = 0; mt < 2; mt++) {
                    mma16n8k16_bf16(acc[mt][nt], ah[mt], bl);
                    mma16n8k16_bf16(acc[mt][nt], al[mt], bh);
                    mma16n8k16_bf16(acc[mt][nt], ah[mt], bh);
                }
            }
        }
    }
}

// Fused QKV: blockIdx.x in [0,24): mat = bx>>3, n-tile = bx&7. Head-split out.
__global__ __launch_bounds__(256, 2) void gemm_qkv(
    const uint4* __restrict__ Ap, const uint4* __restrict__ Wp,
    float* __restrict__ Qo, float* __restrict__ Ko, float* __restrict__ Vo)
{
    const int mat = blockIdx.x >> 3;
    const int n0  = (blockIdx.x & 7) * 128;
    const int m0  = blockIdx.y * 128;
    const uint4* W = Wp + (size_t)mat * Dv * 256;
    float* C = (mat == 0) ? Qo : (mat == 1) ? Ko : Vo;

    float acc[2][8][4];
    #pragma unroll
    for (int mt = 0; mt < 2; mt++)
        #pragma unroll
        for (int nt = 0; nt < 8; nt++)
            #pragma unroll
            for (int i = 0; i < 4; i++) acc[mt][nt][i] = 0.f;

    gemm_core(Ap, W, m0, n0, acc);

    const int wid = threadIdx.x >> 5, lane = threadIdx.x & 31;
    const int wm = wid & 3, wn = wid >> 2;
    const int g = lane >> 2, tg = lane & 3;
    #pragma unroll
    for (int mt = 0; mt < 2; mt++) {
        #pragma unroll
        for (int nt = 0; nt < 8; nt++) {
            const int m = m0 + wm * 32 + mt * 16 + g;
            const int n = n0 + wn * 64 + nt * 8 + tg * 2;
            const int h = n / HDv, hd = n % HDv;
            const int b0_ = m / Sv, s0_ = m % Sv;
            const int b1_ = (m + 8) / Sv, s1_ = (m + 8) % Sv;
            float2* p0 = (float2*)(C + (size_t)((b0_ * Hv + h) * Sv + s0_) * HDv + hd);
            float2* p1 = (float2*)(C + (size_t)((b1_ * Hv + h) * Sv + s1_) * HDv + hd);
            *p0 = make_float2(acc[mt][nt][0], acc[mt][nt][1]);
            *p1 = make_float2(acc[mt][nt][2], acc[mt][nt][3]);
        }
    }
}

// Output projection: row-major C.
__global__ __launch_bounds__(256, 2) void gemm_out(
    const uint4* __restrict__ Ap, const uint4* __restrict__ Wp,
    float* __restrict__ C)
{
    const int n0 = blockIdx.x * 128;
    const int m0 = blockIdx.y * 128;

    float acc[2][8][4];
    #pragma unroll
    for (int mt = 0; mt < 2; mt++)
        #pragma unroll
        for (int nt = 0; nt < 8; nt++)
            #pragma unroll
            for (int i = 0; i < 4; i++) acc[mt][nt][i] = 0.f;

    gemm_core(Ap, Wp, m0, n0, acc);

    const int wid = threadIdx.x >> 5, lane = threadIdx.x & 31;
    const int wm = wid & 3, wn = wid >> 2;
    const int g = lane >> 2, tg = lane & 3;
    #pragma unroll
    for (int mt = 0; mt < 2; mt++) {
        #pragma unroll
        for (int nt = 0; nt < 8; nt++) {
            const int m = m0 + wm * 32 + mt * 16 + g;
            const int n = n0 + wn * 64 + nt * 8 + tg * 2;
            float2* p0 = (float2*)(C + (size_t)m * Dv + n);
            float2* p1 = (float2*)(C + (size_t)(m + 8) * Dv + n);
            *p0 = make_float2(acc[mt][nt][0], acc[mt][nt][1]);
            *p1 = make_float2(acc[mt][nt][2], acc[mt][nt][3]);
        }
    }
}

// ---------------------------------------------------------------------------
// Tensor-core causal flash attention. 256 threads / 128 q-rows per CTA:
// K/V block staging (loads + split_pack + STS) serves 8 warps instead of 4,
// halving staging cost per query. Per-query math identical to R10.
// grid = (S/128, H, B). Packed bf16 hi/lo epilogue (R10-verified).
// ---------------------------------------------------------------------------
__global__ __launch_bounds__(256) void flash_mma(
    const float* __restrict__ Qg, const float* __restrict__ Kg,
    const float* __restrict__ Vg, uint4* __restrict__ Op,
    const float* __restrict__ slog, const float* __restrict__ sscale)
{
    __shared__ uint32_t Ksh[128][20];
    __shared__ uint32_t Ksl[128][20];
    __shared__ uint32_t Vsh[64][40];
    __shared__ uint32_t Vsl[64][40];

    const int tid  = threadIdx.x;
    const int wid  = tid >> 5, lane = tid & 31;
    const int g    = lane >> 2, tg  = lane & 3;
    const int q0   = blockIdx.x * 128;
    const int h    = blockIdx.y, b = blockIdx.z;

    const float* qbase = Qg + (size_t)(b * Hv + h) * Sv * HDv;
    const float* kbase = Kg + (size_t)(b * Hv + h) * Sv * HDv;
    const float* vbase = Vg + (size_t)(b * Hv + h) * Sv * HDv;

    const int r0 = q0 + wid * 16 + g;   // accum rows (c0,c1)
    const int r1 = r0 + 8;              // (c2,c3)

    const float sc0 = slog[r0] * sscale[h] * 0.17677669529663687f;
    const float sc1 = slog[r1] * sscale[h] * 0.17677669529663687f;

    uint32_t qh[2][4], ql[2][4];
    #pragma unroll
    for (int kc = 0; kc < 2; kc++) {
        const int k0 = kc * 16 + 2 * tg;
        split_pack_bf16(qbase[(size_t)r0 * HDv + k0    ] * sc0,
                        qbase[(size_t)r0 * HDv + k0 + 1] * sc0, qh[kc][0], ql[kc][0]);
        split_pack_bf16(qbase[(size_t)r1 * HDv + k0    ] * sc1,
                        qbase[(size_t)r1 * HDv + k0 + 1] * sc1, qh[kc][1], ql[kc][1]);
        split_pack_bf16(qbase[(size_t)r0 * HDv + k0 + 8] * sc0,
                        qbase[(size_t)r0 * HDv + k0 + 9] * sc0, qh[kc][2], ql[kc][2]);
        split_pack_bf16(qbase[(size_t)r1 * HDv + k0 + 8] * sc1,
                        qbase[(size_t)r1 * HDv + k0 + 9] * sc1, qh[kc][3], ql[kc][3]);
    }

    float m0 = -1e30f, m1 = -1e30f, l0 = 0.f, l1 = 0.f;
    float o[4][4];
    #pragma unroll
    for (int nt2 = 0; nt2 < 4; nt2++)
        #pragma unroll
        for (int i = 0; i < 4; i++) o[nt2][i] = 0.f;

    // V staging map: 256 threads cover 64 key-pairs x 2 hd-halves x 2 c-halves
    const int vp = tid & 63, vhh = (tid >> 6) & 1, vch = tid >> 7;
    const int nblocks = q0 / 128 + 1;

    for (int kt = 0; kt < nblocks; kt++) {
        const int kv0 = kt * 128;
        __syncthreads();
        // stage K: 1024 slots over 256 threads (4 each)
        #pragma unroll
        for (int j = 0; j < 4; j++) {
            const int idx = tid + j * 256;
            const int row = idx >> 3, c4 = idx & 7;
            float4 kv = *(const float4*)(kbase + (size_t)(kv0 + row) * HDv + c4 * 4);
            uint32_t h0, h1, l0_, l1_;
            split_pack_bf16(kv.x, kv.y, h0, l0_);
            split_pack_bf16(kv.z, kv.w, h1, l1_);
            *(uint2*)&Ksh[row][c4 * 2] = make_uint2(h0, h1);
            *(uint2*)&Ksl[row][c4 * 2] = make_uint2(l0_, l1_);
        }
        // stage V: pairs along key; 2 c-slots per thread
        #pragma unroll
        for (int cc = 0; cc < 2; cc++) {
            const int c = vch * 2 + cc;
            float4 v0 = *(const float4*)(vbase + (size_t)(kv0 + 2 * vp    ) * HDv + vhh * 16 + 4 * c);
            float4 v1 = *(const float4*)(vbase + (size_t)(kv0 + 2 * vp + 1) * HDv + vhh * 16 + 4 * c);
            uint32_t w0, w1, w2, w3, x0, x1, x2, x3;
            split_pack_bf16(v0.x, v1.x, w0, x0);
            split_pack_bf16(v0.y, v1.y, w1, x1);
            split_pack_bf16(v0.z, v1.z, w2, x2);
            split_pack_bf16(v0.w, v1.w, w3, x3);
            *(uint4*)&Vsh[vp][vhh * 16 + 4 * c] = make_uint4(w0, w1, w2, w3);
            *(uint4*)&Vsl[vp][vhh * 16 + 4 * c] = make_uint4(x0, x1, x2, x3);
        }
        __syncthreads();

        float s[16][4];
        #pragma unroll
        for (int nt = 0; nt < 16; nt++)
            #pragma unroll
            for (int i = 0; i < 4; i++) s[nt][i] = 0.f;

        #pragma unroll
        for (int kc = 0; kc < 2; kc++) {
            const int kp = kc * 8;
            #pragma unroll
            for (int nt = 0; nt < 16; nt++) {
                const int row = nt * 8 + g;
                uint32_t bh[2], bl[2];
                bh[0] = Ksh[row][kp + tg];  bh[1] = Ksh[row][kp + tg + 4];
                bl[0] = Ksl[row][kp + tg];  bl[1] = Ksl[row][kp + tg + 4];
                mma16n8k16_bf16(s[nt], qh[kc], bl);
                mma16n8k16_bf16(s[nt], ql[kc], bh);
                mma16n8k16_bf16(s[nt], qh[kc], bh);
            }
        }

        // causal mask (only the last block crosses any diagonal)
        if (kt == nblocks - 1) {
            #pragma unroll
            for (int nt = 0; nt < 16; nt++) {
                const int c0 = kv0 + nt * 8 + 2 * tg, c1 = c0 + 1;
                if (c0 > r0) s[nt][0] = -1e30f;
                if (c1 > r0) s[nt][1] = -1e30f;
                if (c0 > r1) s[nt][2] = -1e30f;
                if (c1 > r1) s[nt][3] = -1e30f;
            }
        }

        float rmax0 = -1e30f, rmax1 = -1e30f;
        #pragma unroll
        for (int nt = 0; nt < 16; nt++) {
            rmax0 = fmaxf(rmax0, fmaxf(s[nt][0], s[nt][1]));
            rmax1 = fmaxf(rmax1, fmaxf(s[nt][2], s[nt][3]));
        }
        rmax0 = fmaxf(rmax0, __shfl_xor_sync(0xFFFFFFFFu, rmax0, 1));
        rmax0 = fmaxf(rmax0, __shfl_xor_sync(0xFFFFFFFFu, rmax0, 2));
        rmax1 = fmaxf(rmax1, __shfl_xor_sync(0xFFFFFFFFu, rmax1, 1));
        rmax1 = fmaxf(rmax1, __shfl_xor_sync(0xFFFFFFFFu, rmax1, 2));

        const float nm0 = fmaxf(m0, rmax0), nm1 = fmaxf(m1, rmax1);
        const float corr0 = __expf(m0 - nm0), corr1 = __expf(m1 - nm1);
        m0 = nm0; m1 = nm1;

        float ps0 = 0.f, ps1 = 0.f;
        #pragma unroll
        for (int nt = 0; nt < 16; nt++) {
            s[nt][0] = __expf(s[nt][0] - m0); ps0 += s[nt][0];
            s[nt][1] = __expf(s[nt][1] - m0); ps0 += s[nt][1];
            s[nt][2] = __expf(s[nt][2] - m1); ps1 += s[nt][2];
            s[nt][3] = __expf(s[nt][3] - m1); ps1 += s[nt][3];
        }
        l0 = l0 * corr0 + ps0;
        l1 = l1 * corr1 + ps1;

        #pragma unroll
        for (int nt2 = 0; nt2 < 4; nt2++) {
            o[nt2][0] *= corr0; o[nt2][1] *= corr0;
            o[nt2][2] *= corr1; o[nt2][3] *= corr1;
        }

        #pragma unroll
        for (int kc2 = 0; kc2 < 8; kc2++) {
            uint32_t ph[4], pl[4];
            split_pack_bf16(s[2 * kc2    ][0], s[2 * kc2    ][1], ph[0], pl[0]);
            split_pack_bf16(s[2 * kc2    ][2], s[2 * kc2    ][3], ph[1], pl[1]);
            split_pack_bf16(s[2 * kc2 + 1][0], s[2 * kc2 + 1][1], ph[2], pl[2]);
            split_pack_bf16(s[2 * kc2 + 1][2], s[2 * kc2 + 1][3], ph[3], pl[3]);
            #pragma unroll
            for (int nt2 = 0; nt2 < 4; nt2++) {
                const int n = nt2 * 8 + g;
                uint32_t vh[2], vl[2];
                vh[0] = Vsh[kc2 * 8 + tg][n];  vh[1] = Vsh[kc2 * 8 + tg + 4][n];
                vl[0] = Vsl[kc2 * 8 + tg][n];  vl[1] = Vsl[kc2 * 8 + tg + 4][n];
                mma16n8k16_bf16(o[nt2], ph, vl);
                mma16n8k16_bf16(o[nt2], pl, vh);
                mma16n8k16_bf16(o[nt2], ph, vh);
            }
        }
    }

    l0 += __shfl_xor_sync(0xFFFFFFFFu, l0, 1);
    l0 += __shfl_xor_sync(0xFFFFFFFFu, l0, 2);
    l1 += __shfl_xor_sync(0xFFFFFFFFu, l1, 1);
    l1 += __shfl_xor_sync(0xFFFFFFFFu, l1, 2);
    const float inv0 = 1.f / l0, inv1 = 1.f / l1;

    // packed epilogue: group (c=h, ks, tg); pair slots = o[2ks], o[2ks+1]
    uint4* oprow0 = Op + ((size_t)(b * Sv + r0)) * 256 + h * 8;
    uint4* oprow1 = Op + ((size_t)(b * Sv + r1)) * 256 + h * 8;
    #pragma unroll
    for (int ks = 0; ks < 2; ks++) {
        uint32_t h0, l0_, h1, l1_;
        split_pack_bf16(o[2 * ks][0] * inv0, o[2 * ks][1] * inv0, h0, l0_);
        split_pack_bf16(o[2 * ks + 1][0] * inv0, o[2 * ks + 1][1] * inv0, h1, l1_);
        oprow0[ks * 4 + tg] = make_uint4(h0, h1, l0_, l1_);
        split_pack_bf16(o[2 * ks][2] * inv1, o[2 * ks][3] * inv1, h0, l0_);
        split_pack_bf16(o[2 * ks + 1][2] * inv1, o[2 * ks + 1][3] * inv1, h1, l1_);
        oprow1[ks * 4 + tg] = make_uint4(h0, h1, l0_, l1_);
    }
}

// ---------------------------------------------------------------------------
extern "C" void kernel_launch(void* const* d_in, const int* in_sizes, int n_in,
                              void* d_out, int out_size)
{
    const float* x      = (const float*)d_in[0];
    // d_in[1] = mask (additive causal, -1e9 above diag) -- handled analytically
    const float* slog   = (const float*)d_in[2];
    const float* wq     = (const float*)d_in[3];
    const float* wk     = (const float*)d_in[4];
    const float* wv     = (const float*)d_in[5];
    const float* wo     = (const float*)d_in[6];
    const float* sscale = (const float*)d_in[7];
    float* out = (float*)d_out;

    float *Qp, *Kp, *Vp;
    cudaGetSymbolAddress((void**)&Qp, g_Q);
    cudaGetSymbolAddress((void**)&Kp, g_K);
    cudaGetSymbolAddress((void**)&Vp, g_V);
    uint4 *xp, *wp, *op;
    cudaGetSymbolAddress((void**)&xp, g_xp);
    cudaGetSymbolAddress((void**)&wp, g_wp);
    cudaGetSymbolAddress((void**)&op, g_op);

    static bool attr_set = false;
    if (!attr_set) {
        cudaFuncSetAttribute(gemm_qkv, cudaFuncAttributeMaxDynamicSharedMemorySize, 98304);
        cudaFuncSetAttribute(gemm_out, cudaFuncAttributeMaxDynamicSharedMemorySize, 98304);
        attr_set = true;
    }

    // pack x + 4 weights in one launch
    pack_all<<<Mv + 4 * Dv, 256>>>(x, wq, wk, wv, wo, xp, wp);

    // fused QKV projections: 768 CTAs
    dim3 qgrd(24, Mv / 128);
    gemm_qkv<<<qgrd, 256, 98304>>>(xp, wp, Qp, Kp, Vp);

    dim3 fgrd(Sv / 128, Hv, Bv);     // (16, 32, 2) = 1024 CTAs
    flash_mma<<<fgrd, 256>>>(Qp, Kp, Vp, op, slog, sscale);

    dim3 ogrd(Dv / 128, Mv / 128);
    gemm_out<<<ogrd, 256, 98304>>>(op, wp + 3 * (size_t)Dv * 256, out);
}

// round 13
// speedup vs baseline: 1.0831x; 1.0831x over previous
#include <cuda_runtime.h>
#include <cstdint>

// Problem constants
#define Bv 2
#define Sv 2048
#define Dv 1024
#define Hv 32
#define HDv 32
#define Mv (Bv*Sv)   // 4096

// Scratch (device globals -- no allocation allowed)
__device__ float g_Q[Bv*Hv*Sv*HDv];            // [b,h,s,hd] fp32 (flash packs Q itself)
__device__ uint32_t g_kph[Bv*Hv*Sv*16];        // K packed hi: pair j=(hd2j,2j+1) per key row
__device__ uint32_t g_kpl[Bv*Hv*Sv*16];        // K packed lo
__device__ uint32_t g_vph[Bv*Hv*(Sv/2)*32];    // V packed hi: key-pair p, hd d
__device__ uint32_t g_vpl[Bv*Hv*(Sv/2)*32];    // V packed lo
// packed bf16 hi/lo operand planes (uint4 groups, 256 per row of K=1024)
__device__ uint4 g_xp[Mv * 256];               // x packed
__device__ uint4 g_wp[4][Dv * 256];            // wq,wk,wv,wo packed
__device__ uint4 g_op[Mv * 256];               // attn-out packed (written by flash)

// ---------------------------------------------------------------------------
// bf16 helpers (legacy mma.sync path -- works on plain sm_103 target)
// ---------------------------------------------------------------------------
__device__ __forceinline__ uint32_t pack_bf16x2(float e0, float e1) {
    uint32_t r;
    asm("cvt.rn.bf16x2.f32 %0, %1, %2;" : "=r"(r) : "f"(e1), "f"(e0));
    return r;
}
__device__ __forceinline__ float bf16lo_f(uint32_t u) { return __uint_as_float(u << 16); }
__device__ __forceinline__ float bf16hi_f(uint32_t u) { return __uint_as_float(u & 0xFFFF0000u); }

__device__ __forceinline__ void mma16n8k16_bf16(float* d, const uint32_t* a, const uint32_t* b) {
    asm volatile(
        "mma.sync.aligned.m16n8k16.row.col.f32.bf16.bf16.f32 "
        "{%0,%1,%2,%3}, {%4,%5,%6,%7}, {%8,%9}, {%0,%1,%2,%3};"
        : "+f"(d[0]), "+f"(d[1]), "+f"(d[2]), "+f"(d[3])
        : "r"(a[0]), "r"(a[1]), "r"(a[2]), "r"(a[3]), "r"(b[0]), "r"(b[1]));
}

__device__ __forceinline__ void split_pack_bf16(float e0, float e1, uint32_t& hi, uint32_t& lo) {
    hi = pack_bf16x2(e0, e1);
    lo = pack_bf16x2(e0 - bf16lo_f(hi), e1 - bf16hi_f(hi));
}

__device__ __forceinline__ uint32_t smem_u32(const void* p) {
    uint32_t a;
    asm("{ .reg .u64 t; cvta.to.shared.u64 t, %1; cvt.u32.u64 %0, t; }" : "=r"(a) : "l"(p));
    return a;
}

__device__ __forceinline__ void cp_async16(uint32_t saddr, const void* gptr) {
    asm volatile("cp.async.cg.shared.global [%0], [%1], 16;" :: "r"(saddr), "l"(gptr));
}

// ---------------------------------------------------------------------------
// Fused pack: rows 0..4095 = x; rows 4096.. = the 4 weight matrices.
// ---------------------------------------------------------------------------
__global__ __launch_bounds__(256) void pack_all(
    const float* __restrict__ x,
    const float* __restrict__ wq, const float* __restrict__ wk,
    const float* __restrict__ wv, const float* __restrict__ wo,
    uint4* __restrict__ xp, uint4* __restrict__ wp)
{
    const int bx = blockIdx.x;
    const float* src;
    uint4* dst;
    int row;
    if (bx < Mv) {
        src = x; dst = xp; row = bx;
    } else {
        const int wi = (bx - Mv) >> 10;
        row = (bx - Mv) & 1023;
        src = (wi == 0) ? wq : (wi == 1) ? wk : (wi == 2) ? wv : wo;
        dst = wp + (size_t)wi * Dv * 256;
    }
    const int rem = threadIdx.x;
    const int c = rem >> 3, gidx = rem & 7;
    const int ks = gidx >> 2, tg = gidx & 3;
    const float* p = src + (size_t)row * 1024 + c * 32 + ks * 16 + 2 * tg;
    const float2 a0 = *(const float2*)p;
    const float2 a1 = *(const float2*)(p + 8);
    uint32_t h0, l0, h1, l1;
    split_pack_bf16(a0.x, a0.y, h0, l0);
    split_pack_bf16(a1.x, a1.y, h1, l1);
    dst[(size_t)row * 256 + rem] = make_uint4(h0, h1, l0, l1);
}

// ---------------------------------------------------------------------------
// GEMM core (bf16 3-term, packed operands, cp.async double buffer).
// CTA tile 128x128, K-chunk 32, 8 warps (4m x 2n). Single sync per chunk.
// ---------------------------------------------------------------------------
__device__ __forceinline__ void gemm_core(
    const uint4* __restrict__ Ap, const uint4* __restrict__ Wp,
    int m0, int n0, float acc[2][8][4])
{
    extern __shared__ uint4 sm[];
    const uint32_t sbase = smem_u32(sm);

    const int tid  = threadIdx.x;
    const int wid  = tid >> 5, lane = tid & 31;
    const int wm   = wid & 3,  wn   = wid >> 2;
    const int g    = lane >> 2, tg  = lane & 3;

    auto stage = [&](int c, int buf) {
        #pragma unroll
        for (int i = 0; i < 4; i++) {
            const int j = tid + i * 256;
            const int row = j >> 3, gi = j & 7;
            const uint32_t so = (uint32_t)(buf * 3072 + row * 12 + gi) * 16u;
            cp_async16(sbase + so,
                       Ap + (((size_t)(m0 + row)) << 8) + (c << 3) + gi);
            cp_async16(sbase + so + 1536u * 16u,
                       Wp + (((size_t)(n0 + row)) << 8) + (c << 3) + gi);
        }
        asm volatile("cp.async.commit_group;");
    };

    stage(0, 0);

    for (int c = 0; c < 32; c++) {
        asm volatile("cp.async.wait_group 0;");
        __syncthreads();
        if (c < 31) stage(c + 1, (c + 1) & 1);

        const uint4* SA = sm + (c & 1) * 3072;
        const uint4* SB = SA + 1536;

        #pragma unroll
        for (int ks = 0; ks < 2; ks++) {
            uint32_t ah[2][4], al[2][4];
            #pragma unroll
            for (int mt = 0; mt < 2; mt++) {
                const int r = wm * 32 + mt * 16 + g;
                const uint4 u1 = SA[r * 12 + ks * 4 + tg];
                const uint4 u2 = SA[(r + 8) * 12 + ks * 4 + tg];
                ah[mt][0] = u1.x; ah[mt][1] = u2.x; ah[mt][2] = u1.y; ah[mt][3] = u2.y;
                al[mt][0] = u1.z; al[mt][1] = u2.z; al[mt][2] = u1.w; al[mt][3] = u2.w;
            }
            #pragma unroll
            for (int nt = 0; nt < 8; nt++) {
                const int n = wn * 64 + nt * 8 + g;
                const uint4 ub = SB[n * 12 + ks * 4 + tg];
                uint32_t bh[2] = {ub.x, ub.y};
                uint32_t bl[2] = {ub.z, ub.w};
                #pragma unroll
                for (int mt = 0; mt < 2; mt++) {
                    mma16n8k16_bf16(acc[mt][nt], ah[mt], bl);
                    mma16n8k16_bf16(acc[mt][nt], al[mt], bh);
                    mma16n8k16_bf16(acc[mt][nt], ah[mt], bh);
                }
            }
        }
    }
}

// Fused QKV. mat 0: Q fp32 head-split. mat 1: K packed hi/lo pair-planes.
// mat 2: V packed key-pair planes (shfl_xor(.,4) pairs rows m, m+1).
__global__ __launch_bounds__(256, 2) void gemm_qkv(
    const uint4* __restrict__ Ap, const uint4* __restrict__ Wp,
    float* __restrict__ Qo,
    uint32_t* __restrict__ kph, uint32_t* __restrict__ kpl,
    uint32_t* __restrict__ vph, uint32_t* __restrict__ vpl)
{
    const int mat = blockIdx.x >> 3;
    const int n0  = (blockIdx.x & 7) * 128;
    const int m0  = blockIdx.y * 128;
    const uint4* W = Wp + (size_t)mat * Dv * 256;

    float acc[2][8][4];
    #pragma unroll
    for (int mt = 0; mt < 2; mt++)
        #pragma unroll
        for (int nt = 0; nt < 8; nt++)
            #pragma unroll
            for (int i = 0; i < 4; i++) acc[mt][nt][i] = 0.f;

    gemm_core(Ap, W, m0, n0, acc);

    const int wid = threadIdx.x >> 5, lane = threadIdx.x & 31;
    const int wm = wid & 3, wn = wid >> 2;
    const int g = lane >> 2, tg = lane & 3;

    if (mat == 0) {
        #pragma unroll
        for (int mt = 0; mt < 2; mt++) {
            #pragma unroll
            for (int nt = 0; nt < 8; nt++) {
                const int m = m0 + wm * 32 + mt * 16 + g;
                const int n = n0 + wn * 64 + nt * 8 + tg * 2;
                const int h = n / HDv, hd = n % HDv;
                const int b0_ = m / Sv, s0_ = m % Sv;
                const int b1_ = (m + 8) / Sv, s1_ = (m + 8) % Sv;
                float2* p0 = (float2*)(Qo + (size_t)((b0_ * Hv + h) * Sv + s0_) * HDv + hd);
                float2* p1 = (float2*)(Qo + (size_t)((b1_ * Hv + h) * Sv + s1_) * HDv + hd);
                *p0 = make_float2(acc[mt][nt][0], acc[mt][nt][1]);
                *p1 = make_float2(acc[mt][nt][2], acc[mt][nt][3]);
            }
        }
    } else if (mat == 1) {
        // K: pairs along hd = exactly the (c0,c1)/(c2,c3) accumulator pairs
        #pragma unroll
        for (int mt = 0; mt < 2; mt++) {
            #pragma unroll
            for (int nt = 0; nt < 8; nt++) {
                const int m = m0 + wm * 32 + mt * 16 + g;
                const int n = n0 + wn * 64 + nt * 8 + tg * 2;
                const int h = n / HDv, j = (n & 31) >> 1;
                const int b0_ = m / Sv, s0_ = m % Sv;
                const int b1_ = (m + 8) / Sv, s1_ = (m + 8) % Sv;
                uint32_t hi, lo;
                size_t i0 = ((size_t)(b0_ * Hv + h) * Sv + s0_) * 16 + j;
                split_pack_bf16(acc[mt][nt][0], acc[mt][nt][1], hi, lo);
                kph[i0] = hi; kpl[i0] = lo;
                size_t i1 = ((size_t)(b1_ * Hv + h) * Sv + s1_) * 16 + j;
                split_pack_bf16(acc[mt][nt][2], acc[mt][nt][3], hi, lo);
                kph[i1] = hi; kpl[i1] = lo;
            }
        }
    } else {
        // V: pairs along key; exchange with lane^4 (g^1) then even-g writes
        #pragma unroll
        for (int mt = 0; mt < 2; mt++) {
            #pragma unroll
            for (int nt = 0; nt < 8; nt++) {
                const float pc0 = __shfl_xor_sync(0xFFFFFFFFu, acc[mt][nt][0], 4);
                const float pc1 = __shfl_xor_sync(0xFFFFFFFFu, acc[mt][nt][1], 4);
                const float pc2 = __shfl_xor_sync(0xFFFFFFFFu, acc[mt][nt][2], 4);
                const float pc3 = __shfl_xor_sync(0xFFFFFFFFu, acc[mt][nt][3], 4);
                if ((g & 1) == 0) {
                    const int m = m0 + wm * 32 + mt * 16 + g;   // even key
                    const int n = n0 + wn * 64 + nt * 8 + tg * 2;
                    const int h = n / HDv, d = n & 31;
                    const int b0_ = m / Sv, s0_ = m % Sv;
                    uint32_t h0, l0, h1, l1;
                    // key pair (m, m+1), cols d, d+1
                    split_pack_bf16(acc[mt][nt][0], pc0, h0, l0);
                    split_pack_bf16(acc[mt][nt][1], pc1, h1, l1);
                    size_t i0 = ((size_t)(b0_ * Hv + h) * (Sv / 2) + (s0_ >> 1)) * 32 + d;
                    *(uint2*)(vph + i0) = make_uint2(h0, h1);
                    *(uint2*)(vpl + i0) = make_uint2(l0, l1);
                    // key pair (m+8, m+9)
                    split_pack_bf16(acc[mt][nt][2], pc2, h0, l0);
                    split_pack_bf16(acc[mt][nt][3], pc3, h1, l1);
                    const int s8 = (m + 8) % Sv, b8 = (m + 8) / Sv;
                    size_t i1 = ((size_t)(b8 * Hv + h) * (Sv / 2) + (s8 >> 1)) * 32 + d;
                    *(uint2*)(vph + i1) = make_uint2(h0, h1);
                    *(uint2*)(vpl + i1) = make_uint2(l0, l1);
                }
            }
        }
    }
}

// Output projection: row-major C.
__global__ __launch_bounds__(256, 2) void gemm_out(
    const uint4* __restrict__ Ap, const uint4* __restrict__ Wp,
    float* __restrict__ C)
{
    const int n0 = blockIdx.x * 128;
    const int m0 = blockIdx.y * 128;

    float acc[2][8][4];
    #pragma unroll
    for (int mt = 0; mt < 2; mt++)
        #pragma unroll
        for (int nt = 0; nt < 8; nt++)
            #pragma unroll
            for (int i = 0; i < 4; i++) acc[mt][nt][i] = 0.f;

    gemm_core(Ap, Wp, m0, n0, acc);

    const int wid = threadIdx.x >> 5, lane = threadIdx.x & 31;
    const int wm = wid & 3, wn = wid >> 2;
    const int g = lane >> 2, tg = lane & 3;
    #pragma unroll
    for (int mt = 0; mt < 2; mt++) {
        #pragma unroll
        for (int nt = 0; nt < 8; nt++) {
            const int m = m0 + wm * 32 + mt * 16 + g;
            const int n = n0 + wn * 64 + nt * 8 + tg * 2;
            float2* p0 = (float2*)(C + (size_t)m * Dv + n);
            float2* p1 = (float2*)(C + (size_t)(m + 8) * Dv + n);
            *p0 = make_float2(acc[mt][nt][0], acc[mt][nt][1]);
            *p1 = make_float2(acc[mt][nt][2], acc[mt][nt][3]);
        }
    }
}

// ---------------------------------------------------------------------------
// Flash attention: K/V arrive PRE-PACKED -> staging = 8 cp.async/thread,
// double-buffered (82KB dynamic smem), single sync per KV block.
// 256 threads / 128 q-rows. Compute identical to R11. Packed output.
// smem layout (uint32 units, per buffer stride 10240):
//   Ksh 0 (128x20), Ksl 2560, Vsh 5120 (64x40), Vsl 7680
// ---------------------------------------------------------------------------
__global__ __launch_bounds__(256) void flash_mma(
    const float* __restrict__ Qg,
    const uint32_t* __restrict__ kph, const uint32_t* __restrict__ kpl,
    const uint32_t* __restrict__ vph, const uint32_t* __restrict__ vpl,
    uint4* __restrict__ Op,
    const float* __restrict__ slog, const float* __restrict__ sscale)
{
    extern __shared__ uint32_t fsm[];
    const uint32_t fbase = smem_u32(fsm);

    const int tid  = threadIdx.x;
    const int wid  = tid >> 5, lane = tid & 31;
    const int g    = lane >> 2, tg  = lane & 3;
    const int q0   = blockIdx.x * 128;
    const int h    = blockIdx.y, b = blockIdx.z;

    const float* qbase = Qg + (size_t)(b * Hv + h) * Sv * HDv;
    const size_t kbase = (size_t)(b * Hv + h) * Sv;          // key-row base
    const size_t vbase = (size_t)(b * Hv + h) * (Sv / 2);    // key-pair base

    const int r0 = q0 + wid * 16 + g;
    const int r1 = r0 + 8;

    auto stageKV = [&](int kt, int buf) {
        const uint32_t bb = fbase + (uint32_t)buf * 40960u;
        // K: 1024 chunks (128 rows x 4 x 2 planes)
        #pragma unroll
        for (int j = 0; j < 4; j++) {
            const int id = tid + j * 256;
            const int row = id >> 3, sub = id & 7, pl = sub >> 2, q = sub & 3;
            const uint32_t* src = (pl ? kpl : kph) + (kbase + kt * 128 + row) * 16 + 4 * q;
            cp_async16(bb + (uint32_t)(pl * 2560 + row * 20 + 4 * q) * 4u, src);
        }
        // V: 1024 chunks (64 pair-rows x 8 x 2 planes)
        #pragma unroll
        for (int j = 0; j < 4; j++) {
            const int id = tid + j * 256;
            const int row = id >> 4, sub = id & 15, pl = sub >> 3, q = sub & 7;
            const uint32_t* src = (pl ? vpl : vph) + (vbase + kt * 64 + row) * 32 + 4 * q;
            cp_async16(bb + (uint32_t)(5120 + pl * 2560 + row * 40 + 4 * q) * 4u, src);
        }
        asm volatile("cp.async.commit_group;");
    };

    stageKV(0, 0);

    const float sc0 = slog[r0] * sscale[h] * 0.17677669529663687f;
    const float sc1 = slog[r1] * sscale[h] * 0.17677669529663687f;

    uint32_t qh[2][4], ql[2][4];
    #pragma unroll
    for (int kc = 0; kc < 2; kc++) {
        const int k0 = kc * 16 + 2 * tg;
        split_pack_bf16(qbase[(size_t)r0 * HDv + k0    ] * sc0,
                        qbase[(size_t)r0 * HDv + k0 + 1] * sc0, qh[kc][0], ql[kc][0]);
        split_pack_bf16(qbase[(size_t)r1 * HDv + k0    ] * sc1,
                        qbase[(size_t)r1 * HDv + k0 + 1] * sc1, qh[kc][1], ql[kc][1]);
        split_pack_bf16(qbase[(size_t)r0 * HDv + k0 + 8] * sc0,
                        qbase[(size_t)r0 * HDv + k0 + 9] * sc0, qh[kc][2], ql[kc][2]);
        split_pack_bf16(qbase[(size_t)r1 * HDv + k0 + 8] * sc1,
                        qbase[(size_t)r1 * HDv + k0 + 9] * sc1, qh[kc][3], ql[kc][3]);
    }

    float m0 = -1e30f, m1 = -1e30f, l0 = 0.f, l1 = 0.f;
    float o[4][4];
    #pragma unroll
    for (int nt2 = 0; nt2 < 4; nt2++)
        #pragma unroll
        for (int i = 0; i < 4; i++) o[nt2][i] = 0.f;

    const int nblocks = q0 / 128 + 1;

    for (int kt = 0; kt < nblocks; kt++) {
        const int kv0 = kt * 128;
        asm volatile("cp.async.wait_group 0;");
        __syncthreads();
        if (kt < nblocks - 1) stageKV(kt + 1, (kt + 1) & 1);

        const uint32_t* Ksh_ = fsm + (kt & 1) * 10240;
        const uint32_t* Ksl_ = Ksh_ + 2560;
        const uint32_t* Vsh_ = Ksh_ + 5120;
        const uint32_t* Vsl_ = Ksh_ + 7680;

        float s[16][4];
        #pragma unroll
        for (int nt = 0; nt < 16; nt++)
            #pragma unroll
            for (int i = 0; i < 4; i++) s[nt][i] = 0.f;

        #pragma unroll
        for (int kc = 0; kc < 2; kc++) {
            const int kp = kc * 8;
            #pragma unroll
            for (int nt = 0; nt < 16; nt++) {
                const int row = nt * 8 + g;
                uint32_t bh[2], bl[2];
                bh[0] = Ksh_[row * 20 + kp + tg];  bh[1] = Ksh_[row * 20 + kp + tg + 4];
                bl[0] = Ksl_[row * 20 + kp + tg];  bl[1] = Ksl_[row * 20 + kp + tg + 4];
                mma16n8k16_bf16(s[nt], qh[kc], bl);
                mma16n8k16_bf16(s[nt], ql[kc], bh);
                mma16n8k16_bf16(s[nt], qh[kc], bh);
            }
        }

        if (kt == nblocks - 1) {
            #pragma unroll
            for (int nt = 0; nt < 16; nt++) {
                const int c0 = kv0 + nt * 8 + 2 * tg, c1 = c0 + 1;
                if (c0 > r0) s[nt][0] = -1e30f;
                if (c1 > r0) s[nt][1] = -1e30f;
                if (c0 > r1) s[nt][2] = -1e30f;
                if (c1 > r1) s[nt][3] = -1e30f;
            }
        }

        float rmax0 = -1e30f, rmax1 = -1e30f;
        #pragma unroll
        for (int nt = 0; nt < 16; nt++) {
            rmax0 = fmaxf(rmax0, fmaxf(s[nt][0], s[nt][1]));
            rmax1 = fmaxf(rmax1, fmaxf(s[nt][2], s[nt][3]));
        }
        rmax0 = fmaxf(rmax0, __shfl_xor_sync(0xFFFFFFFFu, rmax0, 1));
        rmax0 = fmaxf(rmax0, __shfl_xor_sync(0xFFFFFFFFu, rmax0, 2));
        rmax1 = fmaxf(rmax1, __shfl_xor_sync(0xFFFFFFFFu, rmax1, 1));
        rmax1 = fmaxf(rmax1, __shfl_xor_sync(0xFFFFFFFFu, rmax1, 2));

        const float nm0 = fmaxf(m0, rmax0), nm1 = fmaxf(m1, rmax1);
        const float corr0 = __expf(m0 - nm0), corr1 = __expf(m1 - nm1);
        m0 = nm0; m1 = nm1;

        float ps0 = 0.f, ps1 = 0.f;
        #pragma unroll
        for (int nt = 0; nt < 16; nt++) {
            s[nt][0] = __expf(s[nt][0] - m0); ps0 += s[nt][0];
            s[nt][1] = __expf(s[nt][1] - m0); ps0 += s[nt][1];
            s[nt][2] = __expf(s[nt][2] - m1); ps1 += s[nt][2];
            s[nt][3] = __expf(s[nt][3] - m1); ps1 += s[nt][3];
        }
        l0 = l0 * corr0 + ps0;
        l1 = l1 * corr1 + ps1;

        #pragma unroll
        for (int nt2 = 0; nt2 < 4; nt2++) {
            o[nt2][0] *= corr0; o[nt2][1] *= corr0;
            o[nt2][2] *= corr1; o[nt2][3] *= corr1;
        }

        #pragma unroll
        for (int kc2 = 0; kc2 < 8; kc2++) {
            uint32_t ph[4], pl[4];
            split_pack_bf16(s[2 * kc2    ][0], s[2 * kc2    ][1], ph[0], pl[0]);
            split_pack_bf16(s[2 * kc2    ][2], s[2 * kc2    ][3], ph[1], pl[1]);
            split_pack_bf16(s[2 * kc2 + 1][0], s[2 * kc2 + 1][1], ph[2], pl[2]);
            split_pack_bf16(s[2 * kc2 + 1][2], s[2 * kc2 + 1][3], ph[3], pl[3]);
            #pragma unroll
            for (int nt2 = 0; nt2 < 4; nt2++) {
                const int n = nt2 * 8 + g;
                uint32_t vh[2], vl[2];
                vh[0] = Vsh_[(kc2 * 8 + tg) * 40 + n];  vh[1] = Vsh_[(kc2 * 8 + tg + 4) * 40 + n];
                vl[0] = Vsl_[(kc2 * 8 + tg) * 40 + n];  vl[1] = Vsl_[(kc2 * 8 + tg + 4) * 40 + n];
                mma16n8k16_bf16(o[nt2], ph, vl);
                mma16n8k16_bf16(o[nt2], pl, vh);
                mma16n8k16_bf16(o[nt2], ph, vh);
            }
        }
    }

    l0 += __shfl_xor_sync(0xFFFFFFFFu, l0, 1);
    l0 += __shfl_xor_sync(0xFFFFFFFFu, l0, 2);
    l1 += __shfl_xor_sync(0xFFFFFFFFu, l1, 1);
    l1 += __shfl_xor_sync(0xFFFFFFFFu, l1, 2);
    const float inv0 = 1.f / l0, inv1 = 1.f / l1;

    // packed epilogue: group (c=h, ks, tg); pair slots = o[2ks], o[2ks+1]
    uint4* oprow0 = Op + ((size_t)(b * Sv + r0)) * 256 + h * 8;
    uint4* oprow1 = Op + ((size_t)(b * Sv + r1)) * 256 + h * 8;
    #pragma unroll
    for (int ks = 0; ks < 2; ks++) {
        uint32_t h0, l0_, h1, l1_;
        split_pack_bf16(o[2 * ks][0] * inv0, o[2 * ks][1] * inv0, h0, l0_);
        split_pack_bf16(o[2 * ks + 1][0] * inv0, o[2 * ks + 1][1] * inv0, h1, l1_);
        oprow0[ks * 4 + tg] = make_uint4(h0, h1, l0_, l1_);
        split_pack_bf16(o[2 * ks][2] * inv1, o[2 * ks][3] * inv1, h0, l0_);
        split_pack_bf16(o[2 * ks + 1][2] * inv1, o[2 * ks + 1][3] * inv1, h1, l1_);
        oprow1[ks * 4 + tg] = make_uint4(h0, h1, l0_, l1_);
    }
}

// ---------------------------------------------------------------------------
extern "C" void kernel_launch(void* const* d_in, const int* in_sizes, int n_in,
                              void* d_out, int out_size)
{
    const float* x      = (const float*)d_in[0];
    // d_in[1] = mask (additive causal, -1e9 above diag) -- handled analytically
    const float* slog   = (const float*)d_in[2];
    const float* wq     = (const float*)d_in[3];
    const float* wk     = (const float*)d_in[4];
    const float* wv     = (const float*)d_in[5];
    const float* wo     = (const float*)d_in[6];
    const float* sscale = (const float*)d_in[7];
    float* out = (float*)d_out;

    float *Qp;
    cudaGetSymbolAddress((void**)&Qp, g_Q);
    uint32_t *kph, *kpl, *vph, *vpl;
    cudaGetSymbolAddress((void**)&kph, g_kph);
    cudaGetSymbolAddress((void**)&kpl, g_kpl);
    cudaGetSymbolAddress((void**)&vph, g_vph);
    cudaGetSymbolAddress((void**)&vpl, g_vpl);
    uint4 *xp, *wp, *op;
    cudaGetSymbolAddress((void**)&xp, g_xp);
    cudaGetSymbolAddress((void**)&wp, g_wp);
    cudaGetSymbolAddress((void**)&op, g_op);

    static bool attr_set = false;
    if (!attr_set) {
        cudaFuncSetAttribute(gemm_qkv, cudaFuncAttributeMaxDynamicSharedMemorySize, 98304);
        cudaFuncSetAttribute(gemm_out, cudaFuncAttributeMaxDynamicSharedMemorySize, 98304);
        cudaFuncSetAttribute(flash_mma, cudaFuncAttributeMaxDynamicSharedMemorySize, 81920);
        attr_set = true;
    }

    // pack x + 4 weights in one launch
    pack_all<<<Mv + 4 * Dv, 256>>>(x, wq, wk, wv, wo, xp, wp);

    // fused QKV projections: 768 CTAs; K/V written pre-packed for flash
    dim3 qgrd(24, Mv / 128);
    gemm_qkv<<<qgrd, 256, 98304>>>(xp, wp, Qp, kph, kpl, vph, vpl);

    dim3 fgrd(Sv / 128, Hv, Bv);     // (16, 32, 2) = 1024 CTAs
    flash_mma<<<fgrd, 256, 81920>>>(Qp, kph, kpl, vph, vpl, op, slog, sscale);

    dim3 ogrd(Dv / 128, Mv / 128);
    gemm_out<<<ogrd, 256, 98304>>>(op, wp + 3 * (size_t)Dv * 256, out);
}